// round 14
// baseline (speedup 1.0000x reference)
#include <cuda_runtime.h>
#include <cstdint>

// B=8, N=1024, C=768, H=12, D=64.
//
// Mathematical collapse: V = spe_agg broadcast over the sequence axis is
// independent of the attention key index m, so Σ_m softmax(...)·v = v
// (softmax rows sum to exactly 1). The whole module reduces to
//   out[b, n, j] = Σ_c spe_agg[b,c] * W_proj[j,c] + b_proj[j]   (constant in n)
// x and W_qkv are mathematically unused.
//
// Measured store floor: ~25.2 MB output drains at ~3 TB/s effective on this
// part regardless of mechanism (STG / TMA bulk) -> ~8 us. Strategy: one fused
// kernel, 128B-aligned full-line stores, enough blocks to hide the tiny GEMV
// under the store stream.

#define Bk 8
#define Ck 768
#define Nk 1024
#define JS 32                 // j-columns per block: 32 floats = 128 B (line-aligned)
#define JS4 (JS / 4)          // 8 float4
#define NJ (Ck / JS)          // 24 j-slices
#define TPB 256               // 8 warps

__global__ void __launch_bounds__(TPB) fused_kernel(
    const float* __restrict__ spe_agg,   // (B, C)
    const float* __restrict__ W_proj,    // (C, C) row-major
    const float* __restrict__ b_proj,    // (C,)
    float* __restrict__ out)             // (B, N, C)
{
    __shared__ __align__(16) float y_s[JS];

    const int b     = blockIdx.y;        // 0..7
    const int jbase = blockIdx.x * JS;   // 0,32,...,736  (128B-aligned offsets)
    const int tid   = threadIdx.x;
    const int warp  = tid >> 5;          // 0..7
    const int lane  = tid & 31;

    // ---- Phase 1: y[b][jbase .. jbase+31] --------------------------------
    // 8 warps x 4 j's. spe_agg row pinned in registers (6 float4/lane).
    const float4* __restrict__ srow =
        reinterpret_cast<const float4*>(spe_agg + (size_t)b * Ck);
    float4 sreg[6];
    #pragma unroll
    for (int i = 0; i < 6; ++i) sreg[i] = srow[i * 32 + lane];

    #pragma unroll
    for (int jj = 0; jj < 4; ++jj) {
        const int j = jbase + warp * 4 + jj;
        const float4* __restrict__ Wrow =
            reinterpret_cast<const float4*>(W_proj + (size_t)j * Ck);
        float acc = 0.0f;
        #pragma unroll
        for (int i = 0; i < 6; ++i) {
            float4 w = Wrow[i * 32 + lane];
            acc += w.x * sreg[i].x + w.y * sreg[i].y
                 + w.z * sreg[i].z + w.w * sreg[i].w;
        }
        #pragma unroll
        for (int off = 16; off > 0; off >>= 1)
            acc += __shfl_xor_sync(0xffffffffu, acc, off);
        if (lane == 0)
            y_s[warp * 4 + jj] = acc + __ldg(&b_proj[j]);
    }
    __syncthreads();

    // ---- Phase 2: broadcast the 32-float slice over all 1024 n-rows ------
    // thread -> (f4-column f, starting row r0); value pinned in a register.
    // A warp covers 4 rows x one FULL 128B line each (jbase is 128B-aligned),
    // so every STG.128 produces 4 full-line wavefronts. 32 stores/thread.
    const int f  = tid & (JS4 - 1);      // 0..7
    const int r0 = tid >> 3;             // 0..31
    const float4 val = reinterpret_cast<const float4*>(y_s)[f];

    float* obase = out + (size_t)b * Nk * Ck + jbase;
    #pragma unroll
    for (int it = 0; it < Nk / (TPB / JS4); ++it) {      // 32 iterations
        const int r = r0 + it * (TPB / JS4);
        reinterpret_cast<float4*>(obase + (size_t)r * Ck)[f] = val;
    }
}

extern "C" void kernel_launch(void* const* d_in, const int* in_sizes, int n_in,
                              void* d_out, int out_size)
{
    // metadata order: x, spe_agg, W_qkv, W_proj, b_proj
    const float* spe_agg = (const float*)d_in[1];
    const float* W_proj  = (const float*)d_in[3];
    const float* b_proj  = (const float*)d_in[4];
    float* out           = (float*)d_out;

    (void)in_sizes; (void)n_in; (void)out_size;

    dim3 grid(NJ, Bk);                    // (24, 8) = 192 blocks
    fused_kernel<<<grid, TPB>>>(spe_agg, W_proj, b_proj, out);
}